// round 15
// baseline (speedup 1.0000x reference)
#include <cuda_runtime.h>
#include <math.h>

#define HH 16
#define DDIM 128
#define NB 1024
#define ML 512
#define QL 2048
#define DMODEL 2048
#define GBAND 256

// ------------------------------------------------------------------
// Device scratch (globals: no allocation allowed)
// ------------------------------------------------------------------
__device__ float g_G[ML * NB];            // G[l][n]
__device__ float g_B[NB * DMODEL];        // B[n][d]
__device__ float g_keys[HH * NB * DDIM];  // [h][n][dd]
__device__ float g_vals[HH * NB * DDIM];
__device__ float g_kmu[HH * DDIM];
__device__ float g_ksig[HH * DDIM];
__device__ float g_mu[HH * QL];
__device__ float g_i0[HH * QL];
__device__ float g_i1[HH * QL];
__device__ float g_c0[HH * QL];
__device__ float g_c1[HH * QL];
__device__ float g_ctx[QL * DMODEL];      // context[q][h*128+dd]

// ------------------------------------------------------------------
// Shared GEMM microkernel: 128x128 tile, BK=16, 256 threads, 8x8/thread
// ------------------------------------------------------------------
__device__ __forceinline__ void mainloop16(const float (*As)[132], const float (*Bs)[132],
                                           float acc[8][8], int tx, int ty) {
#pragma unroll
    for (int kk = 0; kk < 16; kk++) {
        float a[8], b[8];
        *(float4*)(a)     = *(const float4*)&As[kk][ty * 8];
        *(float4*)(a + 4) = *(const float4*)&As[kk][ty * 8 + 4];
        *(float4*)(b)     = *(const float4*)&Bs[kk][tx * 8];
        *(float4*)(b + 4) = *(const float4*)&Bs[kk][tx * 8 + 4];
#pragma unroll
        for (int i = 0; i < 8; i++)
#pragma unroll
            for (int j = 0; j < 8; j++)
                acc[i][j] = fmaf(a[i], b[j], acc[i][j]);
    }
}

// ------------------------------------------------------------------
// K1: B[n][d] = sum_l G[l][n] * k[l][d]    (TN gemm, M=1024,N=2048,K=512)
// ------------------------------------------------------------------
__global__ __launch_bounds__(256) void k1_B(const float* __restrict__ Kin) {
    __shared__ __align__(16) float As[16][132];
    __shared__ __align__(16) float Bs[16][132];
    const int t = threadIdx.x;
    const int tx = t & 15, ty = t >> 4;
    const int m0 = blockIdx.y * 128;  // basis n
    const int n0 = blockIdx.x * 128;  // d
    float acc[8][8];
#pragma unroll
    for (int i = 0; i < 8; i++)
#pragma unroll
        for (int j = 0; j < 8; j++) acc[i][j] = 0.f;

    for (int k0 = 0; k0 < ML; k0 += 16) {
#pragma unroll
        for (int i = 0; i < 2; i++) {
            int slot = t + 256 * i;
            int kk = slot >> 5, mq = slot & 31;
            *(float4*)&As[kk][mq * 4] = *(const float4*)(g_G + (size_t)(k0 + kk) * NB + m0 + mq * 4);
            *(float4*)&Bs[kk][mq * 4] = *(const float4*)(Kin + (size_t)(k0 + kk) * DMODEL + n0 + mq * 4);
        }
        __syncthreads();
        mainloop16(As, Bs, acc, tx, ty);
        __syncthreads();
    }
#pragma unroll
    for (int i = 0; i < 8; i++) {
        int row = m0 + ty * 8 + i;
        float4 v0 = {acc[i][0], acc[i][1], acc[i][2], acc[i][3]};
        float4 v1 = {acc[i][4], acc[i][5], acc[i][6], acc[i][7]};
        *(float4*)(g_B + (size_t)row * DMODEL + n0 + tx * 8)     = v0;
        *(float4*)(g_B + (size_t)row * DMODEL + n0 + tx * 8 + 4) = v1;
    }
}

// ------------------------------------------------------------------
// K2: keys/vals[h][n][dd] = sum_d B[n][d]*W[e][d], e = h*128+dd
// NT gemm, M=1024 (n), N=2048 (e), K=2048. grid.z selects Wk/Wv.
// ------------------------------------------------------------------
__global__ __launch_bounds__(256) void k2_kv(const float* __restrict__ Wk,
                                             const float* __restrict__ Wv) {
    __shared__ __align__(16) float As[16][132];
    __shared__ __align__(16) float Bs[16][132];
    const float* W = (blockIdx.z == 0) ? Wk : Wv;
    float* out = (blockIdx.z == 0) ? g_keys : g_vals;
    const int t = threadIdx.x;
    const int tx = t & 15, ty = t >> 4;
    const int m0 = blockIdx.y * 128;  // basis n
    const int n0 = blockIdx.x * 128;  // e
    float acc[8][8];
#pragma unroll
    for (int i = 0; i < 8; i++)
#pragma unroll
        for (int j = 0; j < 8; j++) acc[i][j] = 0.f;

    for (int k0 = 0; k0 < DMODEL; k0 += 16) {
#pragma unroll
        for (int i = 0; i < 2; i++) {
            int slot = t + 256 * i;
            int row = slot >> 2, kq = slot & 3;
            float4 va = *(const float4*)(g_B + (size_t)(m0 + row) * DMODEL + k0 + kq * 4);
            As[kq * 4 + 0][row] = va.x; As[kq * 4 + 1][row] = va.y;
            As[kq * 4 + 2][row] = va.z; As[kq * 4 + 3][row] = va.w;
            float4 vb = *(const float4*)(W + (size_t)(n0 + row) * DMODEL + k0 + kq * 4);
            Bs[kq * 4 + 0][row] = vb.x; Bs[kq * 4 + 1][row] = vb.y;
            Bs[kq * 4 + 2][row] = vb.z; Bs[kq * 4 + 3][row] = vb.w;
        }
        __syncthreads();
        mainloop16(As, Bs, acc, tx, ty);
        __syncthreads();
    }
    const size_t base = (size_t)(n0 >> 7) * NB * DDIM;  // head offset
#pragma unroll
    for (int i = 0; i < 8; i++) {
        int row = m0 + ty * 8 + i;
        float4 v0 = {acc[i][0], acc[i][1], acc[i][2], acc[i][3]};
        float4 v1 = {acc[i][4], acc[i][5], acc[i][6], acc[i][7]};
        *(float4*)(out + base + (size_t)row * DDIM + tx * 8)     = v0;
        *(float4*)(out + base + (size_t)row * DDIM + tx * 8 + 4) = v1;
    }
}

// ------------------------------------------------------------------
// K3: kmu[h][dd] = sum_n keys[h][n][dd]*w_mu[n];  ksig likewise
// ------------------------------------------------------------------
__global__ void k3_kvred(const float* __restrict__ wmu, const float* __restrict__ wsig) {
    int h = blockIdx.x;
    int dd = threadIdx.x;  // 128 threads
    const float* Kp = g_keys + (size_t)h * NB * DDIM + dd;
    float s1 = 0.f, s2 = 0.f;
#pragma unroll 4
    for (int n = 0; n < NB; n++) {
        float kv = Kp[(size_t)n * DDIM];
        s1 = fmaf(kv, __ldg(wmu + n), s1);
        s2 = fmaf(kv, __ldg(wsig + n), s2);
    }
    g_kmu[h * DDIM + dd] = s1;
    g_ksig[h * DDIM + dd] = s2;
}

// ------------------------------------------------------------------
// K4: per (h,q): mu = sigmoid(q.kmu/sqrtD), sigma_sq = max(softplus(q.ksig/sqrtD),1e-4)
//     precompute 1/s and coef = 1/(s*sqrt(2pi)) for both b_sigma families
// ------------------------------------------------------------------
__global__ __launch_bounds__(256) void k4_mu(const float* __restrict__ q) {
    int warp = threadIdx.x >> 5, lane = threadIdx.x & 31;
    int row = blockIdx.x * 8 + warp;           // 0..32767 (h-major)
    int h = row >> 11, qq = row & (QL - 1);
    const float* qp = q + ((size_t)h * QL + qq) * DDIM;
    float4 v = *(const float4*)(qp + lane * 4);
    float4 a = *(const float4*)(g_kmu + h * DDIM + lane * 4);
    float4 b = *(const float4*)(g_ksig + h * DDIM + lane * 4);
    float s1 = v.x * a.x + v.y * a.y + v.z * a.z + v.w * a.w;
    float s2 = v.x * b.x + v.y * b.y + v.z * b.z + v.w * b.w;
#pragma unroll
    for (int o = 16; o; o >>= 1) {
        s1 += __shfl_down_sync(0xffffffffu, s1, o);
        s2 += __shfl_down_sync(0xffffffffu, s2, o);
    }
    if (lane == 0) {
        const float scale = 0.08838834764831845f;  // 1/sqrt(128)
        float x1 = s1 * scale, x2 = s2 * scale;
        float muv = 1.f / (1.f + expf(-x1));
        float sp = (x2 > 20.f) ? x2 : log1pf(expf(x2));
        float ssq = fmaxf(sp, 1e-4f);
        float s0 = sqrtf(ssq + 0.005f * 0.005f);
        float sA = sqrtf(ssq + 0.01f * 0.01f);
        const float ic = 0.3989422804014327f;  // 1/sqrt(2pi)
        g_mu[row] = muv;
        g_i0[row] = 1.f / s0;  g_i1[row] = 1.f / sA;
        g_c0[row] = ic / s0;   g_c1[row] = ic / sA;
    }
}

// ------------------------------------------------------------------
// K5: context[q][h*128+dd] = sum_n r(h,q,n)*vals[h][n][dd]
//     r generated on the fly in the A-tile (with exp cutoff)
// ------------------------------------------------------------------
__global__ __launch_bounds__(256) void k5_ctx() {
    __shared__ __align__(16) float As[16][132];
    __shared__ __align__(16) float Bs[16][132];
    const int h = blockIdx.y;
    const int m0 = blockIdx.x * 128;  // q
    const int t = threadIdx.x;
    const int tx = t & 15, ty = t >> 4;
    const int qq = t & 127;
    const int base = h * QL + m0 + qq;
    const float mu = g_mu[base];
    const float i0 = g_i0[base], i1 = g_i1[base];
    const float c0 = g_c0[base], c1 = g_c1[base];
    const int kof = t >> 7;  // 0 or 1
    const float* V = g_vals + (size_t)h * NB * DDIM;
    float acc[8][8];
#pragma unroll
    for (int i = 0; i < 8; i++)
#pragma unroll
        for (int j = 0; j < 8; j++) acc[i][j] = 0.f;

    for (int n0 = 0; n0 < NB; n0 += 16) {
#pragma unroll
        for (int i = 0; i < 2; i++) {
            int slot = t + 256 * i;
            int kk = slot >> 5, dq = slot & 31;
            *(float4*)&Bs[kk][dq * 4] = *(const float4*)(V + (size_t)(n0 + kk) * DDIM + dq * 4);
        }
#pragma unroll
        for (int i = 0; i < 8; i++) {
            int kk = kof + 2 * i;
            int n = n0 + kk;
            float bm = (float)(n >> 1) * (1.0f / 511.0f);
            float invs = (n & 1) ? i1 : i0;
            float coef = (n & 1) ? c1 : c0;
            float dz = (bm - mu) * invs;
            float z2 = dz * dz;
            float rv = 0.f;
            if (z2 < 88.f) rv = __expf(-0.5f * z2) * coef;
            As[kk][qq] = rv;
        }
        __syncthreads();
        mainloop16(As, Bs, acc, tx, ty);
        __syncthreads();
    }
#pragma unroll
    for (int i = 0; i < 8; i++) {
        int row = m0 + ty * 8 + i;
        float4 v0 = {acc[i][0], acc[i][1], acc[i][2], acc[i][3]};
        float4 v1 = {acc[i][4], acc[i][5], acc[i][6], acc[i][7]};
        *(float4*)(g_ctx + (size_t)row * DMODEL + h * DDIM + tx * 8)     = v0;
        *(float4*)(g_ctx + (size_t)row * DMODEL + h * DDIM + tx * 8 + 4) = v1;
    }
}

// ------------------------------------------------------------------
// K6: out[q][e] = sum_c ctx[q][c]*Wo[e][c]  (NT, 2048x2048x2048)
// ------------------------------------------------------------------
__global__ __launch_bounds__(256) void k6_out(const float* __restrict__ Wo,
                                              float* __restrict__ C) {
    __shared__ __align__(16) float As[16][132];
    __shared__ __align__(16) float Bs[16][132];
    const int t = threadIdx.x;
    const int tx = t & 15, ty = t >> 4;
    const int m0 = blockIdx.y * 128;
    const int n0 = blockIdx.x * 128;
    float acc[8][8];
#pragma unroll
    for (int i = 0; i < 8; i++)
#pragma unroll
        for (int j = 0; j < 8; j++) acc[i][j] = 0.f;

    for (int k0 = 0; k0 < DMODEL; k0 += 16) {
#pragma unroll
        for (int i = 0; i < 2; i++) {
            int slot = t + 256 * i;
            int row = slot >> 2, kq = slot & 3;
            float4 va = *(const float4*)(g_ctx + (size_t)(m0 + row) * DMODEL + k0 + kq * 4);
            As[kq * 4 + 0][row] = va.x; As[kq * 4 + 1][row] = va.y;
            As[kq * 4 + 2][row] = va.z; As[kq * 4 + 3][row] = va.w;
            float4 vb = *(const float4*)(Wo + (size_t)(n0 + row) * DMODEL + k0 + kq * 4);
            Bs[kq * 4 + 0][row] = vb.x; Bs[kq * 4 + 1][row] = vb.y;
            Bs[kq * 4 + 2][row] = vb.z; Bs[kq * 4 + 3][row] = vb.w;
        }
        __syncthreads();
        mainloop16(As, Bs, acc, tx, ty);
        __syncthreads();
    }
#pragma unroll
    for (int i = 0; i < 8; i++) {
        int row = m0 + ty * 8 + i;
        float4 v0 = {acc[i][0], acc[i][1], acc[i][2], acc[i][3]};
        float4 v1 = {acc[i][4], acc[i][5], acc[i][6], acc[i][7]};
        *(float4*)(C + (size_t)row * DMODEL + n0 + tx * 8)     = v0;
        *(float4*)(C + (size_t)row * DMODEL + n0 + tx * 8 + 4) = v1;
    }
}

// ------------------------------------------------------------------
// Host: compute G = solve(F F^T + 0.5 I, F).T[256:768]  (input-independent)
// F is computed in f32 to mirror the reference; the Gram matrix is exactly
// banded in f32 (Gaussian tails underflow), so a banded double Cholesky
// reproduces the exact ridge solution.
// ------------------------------------------------------------------
static double hF[NB * NB];   // [basis][pos]
static double hA[NB * NB];   // Gram + ridge, then Cholesky factor (banded)
static double hX[NB * ML];   // RHS -> solution [basis][l]
static float h_G[ML * NB];   // G[l][n]

static void compute_G_host() {
    float bmu[NB], bsg[NB], pos[NB];
    for (int i = 0; i < 512; i++) {
        float m = (float)i * (1.0f / 511.0f);
        bmu[2 * i] = m; bmu[2 * i + 1] = m;
    }
    bmu[1022] = 1.0f; bmu[1023] = 1.0f;  // linspace endpoint exact
    for (int i = 0; i < NB; i++) bsg[i] = (i & 1) ? 0.01f : 0.005f;
    {
        float start = -0.4990234375f, stop = 1.4990234375f;  // +-0.5 -/+ 1/1024 (exact)
        float step = (stop - start) / 1023.0f;
        for (int i = 0; i < NB; i++) pos[i] = start + (float)i * step;
        pos[NB - 1] = stop;
    }
    float s2pi = sqrtf(6.283185307179586f);
    for (int i = 0; i < NB; i++) {
        float sg = bsg[i], mu = bmu[i];
        float den = sg * s2pi;
        for (int p = 0; p < NB; p++) {
            float z = (pos[p] - mu) / sg;
            float e = expf(-0.5f * z * z);
            hF[(size_t)i * NB + p] = (double)(e / den);
        }
    }
    // A = F F^T + 0.5 I (banded; out-of-band products are exactly 0 in f32)
    for (int i = 0; i < NB; i++) {
        int j0 = i - GBAND; if (j0 < 0) j0 = 0;
        const double* fi = hF + (size_t)i * NB;
        for (int j = j0; j <= i; j++) {
            const double* fj = hF + (size_t)j * NB;
            double s = 0.0;
            for (int p = 0; p < NB; p++) s += fi[p] * fj[p];
            if (i == j) s += 0.5;
            hA[(size_t)i * NB + j] = s;
            hA[(size_t)j * NB + i] = s;
        }
    }
    // Banded Cholesky (lower, in place)
    for (int j = 0; j < NB; j++) {
        int k0 = j - GBAND; if (k0 < 0) k0 = 0;
        double d = hA[(size_t)j * NB + j];
        for (int k = k0; k < j; k++) { double v = hA[(size_t)j * NB + k]; d -= v * v; }
        d = sqrt(d);
        hA[(size_t)j * NB + j] = d;
        double inv = 1.0 / d;
        int iend = j + GBAND; if (iend > NB - 1) iend = NB - 1;
        for (int i = j + 1; i <= iend; i++) {
            int kk0 = i - GBAND; if (kk0 < 0) kk0 = 0;
            double s = hA[(size_t)i * NB + j];
            for (int k = kk0; k < j; k++) s -= hA[(size_t)i * NB + k] * hA[(size_t)j * NB + k];
            hA[(size_t)i * NB + j] = s * inv;
        }
    }
    // RHS: only the 512 pos-columns [256,768) are needed (G row slice)
    for (int i = 0; i < NB; i++)
        for (int l = 0; l < ML; l++) hX[(size_t)i * ML + l] = hF[(size_t)i * NB + 256 + l];
    // Forward solve L Y = RHS (vectorized over RHS)
    for (int i = 0; i < NB; i++) {
        double* yi = hX + (size_t)i * ML;
        int k0 = i - GBAND; if (k0 < 0) k0 = 0;
        for (int k = k0; k < i; k++) {
            double lik = hA[(size_t)i * NB + k];
            const double* yk = hX + (size_t)k * ML;
            for (int c = 0; c < ML; c++) yi[c] -= lik * yk[c];
        }
        double inv = 1.0 / hA[(size_t)i * NB + i];
        for (int c = 0; c < ML; c++) yi[c] *= inv;
    }
    // Back solve L^T X = Y
    for (int i = NB - 1; i >= 0; i--) {
        double* xi = hX + (size_t)i * ML;
        int kend = i + GBAND; if (kend > NB - 1) kend = NB - 1;
        for (int k = i + 1; k <= kend; k++) {
            double lki = hA[(size_t)k * NB + i];
            const double* xk = hX + (size_t)k * ML;
            for (int c = 0; c < ML; c++) xi[c] -= lki * xk[c];
        }
        double inv = 1.0 / hA[(size_t)i * NB + i];
        for (int c = 0; c < ML; c++) xi[c] *= inv;
    }
    // G[l][n] = X[n][l]
    for (int n = 0; n < NB; n++)
        for (int l = 0; l < ML; l++) h_G[(size_t)l * NB + n] = (float)hX[(size_t)n * ML + l];
}

// ------------------------------------------------------------------
extern "C" void kernel_launch(void* const* d_in, const int* in_sizes, int n_in,
                              void* d_out, int out_size) {
    const float* dK   = (const float*)d_in[0];  // k   (1,512,2048)
    const float* dQ   = (const float*)d_in[1];  // q   (1,16,2048,128)
    const float* dWk  = (const float*)d_in[2];
    const float* dWv  = (const float*)d_in[3];
    const float* dWo  = (const float*)d_in[4];
    const float* dwmu = (const float*)d_in[5];
    const float* dwsg = (const float*)d_in[6];
    float* dOut = (float*)d_out;
    (void)in_sizes; (void)n_in; (void)out_size;

    // Input-independent constant; recomputed deterministically every call.
    compute_G_host();
    cudaMemcpyToSymbolAsync(g_G, h_G, sizeof(h_G), 0, cudaMemcpyHostToDevice, 0);

    k1_B<<<dim3(16, 8), 256>>>(dK);
    k2_kv<<<dim3(16, 8, 2), 256>>>(dWk, dWv);
    k3_kvred<<<16, 128>>>(dwmu, dwsg);
    k4_mu<<<(HH * QL) / 8, 256>>>(dQ);
    k5_ctx<<<dim3(16, HH), 256>>>();
    k6_out<<<dim3(16, 16), 256>>>(dWo, dOut);
}